// round 2
// baseline (speedup 1.0000x reference)
#include <cuda_runtime.h>
#include <cstdint>

#define NN 500000
#define FF 128
#define HH 256
#define CC 40
#define IPB 2048                       // items per scan block (256 thr x 8)
#define NBLK ((NN + IPB - 1) / IPB)    // 245

static_assert(NBLK <= 256, "scan2 single block");

// ---- scratch (device globals; no allocations allowed) ----
__device__ int g_first_pos[NN];
__device__ int g_excl[NN];
__device__ int g_bsum[NBLK];
__device__ int g_bsumx[NBLK];
__device__ int g_mapped[NN];
__device__ int g_U;
__device__ __align__(128) float g_agg[(size_t)NN * HH];   // 512 MB

// ---------------- mapping pipeline ----------------

__global__ void k_init_firstpos() {
    int i = blockIdx.x * blockDim.x + threadIdx.x;
    if (i < NN) g_first_pos[i] = NN;
}

__global__ void k_firstpos(const int* __restrict__ ei) {
    int i = blockIdx.x * blockDim.x + threadIdx.x;
    if (i < NN) atomicMin(&g_first_pos[ei[2 * i]], i);
}

// flags + block-partial exclusive scan
__global__ __launch_bounds__(256) void k_scan1(const int* __restrict__ ei) {
    int t = threadIdx.x, b = blockIdx.x;
    int base = b * IPB + t * 8;
    int f[8]; int ls = 0;
#pragma unroll
    for (int j = 0; j < 8; j++) {
        int i = base + j;
        int v = 0;
        if (i < NN) { int s = ei[2 * i]; v = (g_first_pos[s] == i) ? 1 : 0; }
        f[j] = v; ls += v;
    }
    int lane = t & 31, wid = t >> 5;
    int incl = ls;
#pragma unroll
    for (int o = 1; o < 32; o <<= 1) {
        int n = __shfl_up_sync(0xffffffffu, incl, o);
        if (lane >= o) incl += n;
    }
    __shared__ int wtot[8], woff[8];
    if (lane == 31) wtot[wid] = incl;
    __syncthreads();
    if (t < 8) {
        int s = 0;
        for (int j = 0; j < t; j++) s += wtot[j];
        woff[t] = s;
    }
    __syncthreads();
    int run = woff[wid] + (incl - ls);
#pragma unroll
    for (int j = 0; j < 8; j++) {
        int i = base + j;
        if (i < NN) g_excl[i] = run;
        run += f[j];
    }
    if (t == 255) g_bsum[b] = run;   // block total
}

// scan of block sums (single block) + total U
__global__ __launch_bounds__(256) void k_scan2() {
    int t = threadIdx.x;
    int v = (t < NBLK) ? g_bsum[t] : 0;
    int lane = t & 31, wid = t >> 5;
    int incl = v;
#pragma unroll
    for (int o = 1; o < 32; o <<= 1) {
        int n = __shfl_up_sync(0xffffffffu, incl, o);
        if (lane >= o) incl += n;
    }
    __shared__ int wtot[8], woff[8];
    if (lane == 31) wtot[wid] = incl;
    __syncthreads();
    if (t < 8) {
        int s = 0;
        for (int j = 0; j < t; j++) s += wtot[j];
        woff[t] = s;
    }
    __syncthreads();
    int excl = woff[wid] + incl - v;
    if (t < NBLK) g_bsumx[t] = excl;
    if (t == 255) g_U = excl + v;    // total unique count
}

__global__ void k_mapped(const int* __restrict__ ei) {
    int i = blockIdx.x * blockDim.x + threadIdx.x;
    if (i < NN) {
        int j  = ei[2 * i];
        int s2 = ei[2 * j];
        int p  = g_first_pos[s2];            // valid: s2 appears in seg
        g_mapped[i] = g_excl[p] + g_bsumx[p / IPB];
    }
}

// zero only the live segment rows [0, U)
__global__ void k_zero_agg() {
    size_t total = (size_t)g_U * HH / 4;     // float4 count
    float4* p = (float4*)g_agg;
    float4 z = make_float4(0.f, 0.f, 0.f, 0.f);
    for (size_t i = blockIdx.x * (size_t)blockDim.x + threadIdx.x; i < total;
         i += (size_t)gridDim.x * blockDim.x)
        p[i] = z;
}

// ---------------- GEMM1 (relu(x@W1+b1)) fused with segment scatter ----------------
// 128x128x16 tile, 256 threads, 8x8 per thread, fp32.
__global__ __launch_bounds__(256) void k_gemm1_scatter(
    const float* __restrict__ x, const float* __restrict__ W1,
    const float* __restrict__ b1) {
    __shared__ float As[16][128];
    __shared__ float Bs[16][128];
    int t = threadIdx.x;
    int rowBase = blockIdx.x * 128;
    int colBase = blockIdx.y * 128;
    int tx = t & 15, ty = t >> 4;
    int m0 = ty * 8, n0 = tx * 8;

    float acc[8][8];
#pragma unroll
    for (int i = 0; i < 8; i++)
#pragma unroll
        for (int j = 0; j < 8; j++) acc[i][j] = 0.f;

    float bv[8];
#pragma unroll
    for (int c = 0; c < 8; c++) bv[c] = b1[colBase + n0 + c];

    for (int kk = 0; kk < FF; kk += 16) {
        // A tile: 128 rows x 16 k, store transposed As[k][m]
#pragma unroll
        for (int q = t; q < 512; q += 256) {
            int r = q >> 2, c4 = q & 3;
            int grow = rowBase + r;
            float4 v = make_float4(0.f, 0.f, 0.f, 0.f);
            if (grow < NN)
                v = *(const float4*)&x[(size_t)grow * FF + kk + c4 * 4];
            As[c4 * 4 + 0][r] = v.x;
            As[c4 * 4 + 1][r] = v.y;
            As[c4 * 4 + 2][r] = v.z;
            As[c4 * 4 + 3][r] = v.w;
        }
        // B tile: 16 k x 128 n
#pragma unroll
        for (int q = t; q < 512; q += 256) {
            int r = q >> 5, c4 = q & 31;
            float4 v = *(const float4*)&W1[(size_t)(kk + r) * HH + colBase + c4 * 4];
            *(float4*)&Bs[r][c4 * 4] = v;
        }
        __syncthreads();
#pragma unroll
        for (int k = 0; k < 16; k++) {
            float a[8], bb[8];
            *(float4*)&a[0]  = *(float4*)&As[k][m0];
            *(float4*)&a[4]  = *(float4*)&As[k][m0 + 4];
            *(float4*)&bb[0] = *(float4*)&Bs[k][n0];
            *(float4*)&bb[4] = *(float4*)&Bs[k][n0 + 4];
#pragma unroll
            for (int i = 0; i < 8; i++)
#pragma unroll
                for (int j = 0; j < 8; j++) acc[i][j] += a[i] * bb[j];
        }
        __syncthreads();
    }

    // epilogue: bias + relu + scatter-add into agg[mapped[row]]
#pragma unroll
    for (int i = 0; i < 8; i++) {
        int grow = rowBase + m0 + i;
        if (grow < NN) {
            int tgt = g_mapped[grow];
            float* dst = g_agg + (size_t)tgt * HH + colBase + n0;
            float v[8];
#pragma unroll
            for (int j = 0; j < 8; j++) {
                float h = acc[i][j] + bv[j];
                v[j] = h > 0.f ? h : 0.f;
            }
            asm volatile("red.global.add.v4.f32 [%0], {%1,%2,%3,%4};" ::
                         "l"(dst), "f"(v[0]), "f"(v[1]), "f"(v[2]), "f"(v[3])
                         : "memory");
            asm volatile("red.global.add.v4.f32 [%0], {%1,%2,%3,%4};" ::
                         "l"(dst + 4), "f"(v[4]), "f"(v[5]), "f"(v[6]), "f"(v[7])
                         : "memory");
        }
    }
}

// ---------------- GEMM2: out = relu(agg) @ W2 + b2 ----------------
// 64-row tiles; k staged in 64-chunks; thread = (col in [0,32), 8 rows), 2 cols each.
__global__ __launch_bounds__(256) void k_gemm2(
    const float* __restrict__ W2, const float* __restrict__ b2,
    float* __restrict__ out) {
    __shared__ float sW[64][64];   // k-chunk x padded cols
    __shared__ float sA[64][64];   // rows x k-chunk
    int t = threadIdx.x;
    int rowBase = blockIdx.x * 64;
    int U = g_U;
    int col = t & 31, rowg = t >> 5;

    float acc[8][2];
#pragma unroll
    for (int r = 0; r < 8; r++) { acc[r][0] = 0.f; acc[r][1] = 0.f; }

    for (int kc = 0; kc < 4; kc++) {
        // stage W2 chunk (zero-padded to 64 cols)
#pragma unroll
        for (int q = t; q < 64 * 64; q += 256) {
            int k = q >> 6, c = q & 63;
            sW[k][c] = (c < CC) ? W2[(size_t)(kc * 64 + k) * CC + c] : 0.f;
        }
        // stage relu(agg) chunk; rows >= U are implicit zeros
#pragma unroll
        for (int q = t; q < 64 * 16; q += 256) {
            int r = q >> 4, c4 = q & 15;
            int grow = rowBase + r;
            float4 v = make_float4(0.f, 0.f, 0.f, 0.f);
            if (grow < U) {
                v = *(const float4*)&g_agg[(size_t)grow * HH + kc * 64 + c4 * 4];
                v.x = fmaxf(v.x, 0.f); v.y = fmaxf(v.y, 0.f);
                v.z = fmaxf(v.z, 0.f); v.w = fmaxf(v.w, 0.f);
            }
            *(float4*)&sA[r][c4 * 4] = v;
        }
        __syncthreads();
#pragma unroll
        for (int k4 = 0; k4 < 16; k4++) {
            float w0[4], w1[4];
#pragma unroll
            for (int e = 0; e < 4; e++) {
                w0[e] = sW[k4 * 4 + e][col];
                w1[e] = sW[k4 * 4 + e][col + 32];
            }
#pragma unroll
            for (int r = 0; r < 8; r++) {
                float4 a = *(float4*)&sA[rowg * 8 + r][k4 * 4];
                acc[r][0] += a.x * w0[0] + a.y * w0[1] + a.z * w0[2] + a.w * w0[3];
                acc[r][1] += a.x * w1[0] + a.y * w1[1] + a.z * w1[2] + a.w * w1[3];
            }
        }
        __syncthreads();
    }

    float b2a = b2[col];
    float b2b = (col + 32 < CC) ? b2[col + 32] : 0.f;
#pragma unroll
    for (int r = 0; r < 8; r++) {
        int grow = rowBase + rowg * 8 + r;
        if (grow < NN) {
            out[(size_t)grow * CC + col] = acc[r][0] + b2a;
            if (col + 32 < CC)
                out[(size_t)grow * CC + col + 32] = acc[r][1] + b2b;
        }
    }
}

// ---------------- launch ----------------
extern "C" void kernel_launch(void* const* d_in, const int* in_sizes, int n_in,
                              void* d_out, int out_size) {
    const float* x  = (const float*)d_in[0];
    const int*   ei = (const int*)d_in[1];
    const float* W1 = (const float*)d_in[2];
    const float* b1 = (const float*)d_in[3];
    const float* W2 = (const float*)d_in[4];
    const float* b2 = (const float*)d_in[5];
    float* out = (float*)d_out;

    int nb = (NN + 255) / 256;
    k_init_firstpos<<<nb, 256>>>();
    k_firstpos<<<nb, 256>>>(ei);
    k_scan1<<<NBLK, 256>>>(ei);
    k_scan2<<<1, 256>>>();
    k_mapped<<<nb, 256>>>(ei);
    k_zero_agg<<<2048, 256>>>();

    dim3 g1((NN + 127) / 128, HH / 128);
    k_gemm1_scatter<<<g1, 256>>>(x, W1, b1);

    k_gemm2<<<(NN + 63) / 64, 256>>>(W2, b2, out);
}

// round 6
// speedup vs baseline: 1.6682x; 1.6682x over previous
#include <cuda_runtime.h>
#include <cuda_bf16.h>
#include <cstdint>

#define NN 500000
#define FF 128
#define HH 256
#define CC 40
#define IPB 2048                       // items per scan block (256 thr x 8)
#define NBLK ((NN + IPB - 1) / IPB)    // 245

static_assert(NBLK <= 256, "scan2 single block");

// ---- scratch (device globals; no allocations allowed) ----
__device__ int g_first_pos[NN];
__device__ int g_excl[NN];
__device__ int g_bsum[NBLK];
__device__ int g_bsumx[NBLK];
__device__ int g_mapped[NN];
__device__ int g_U;
__device__ __align__(128) float g_agg[(size_t)NN * HH];   // 512 MB

// pre-split W images, transposed to [n][k] bf16 with ldmatrix-friendly pitch
// pitch1 = 136 bf16 = 272 B (272 % 128 == 16 -> conflict-free ldmatrix)
// pitch2 = 264 bf16 = 528 B (528 % 128 == 16)
__device__ __align__(16) unsigned char g_B1hi[256 * 272];
__device__ __align__(16) unsigned char g_B1lo[256 * 272];
__device__ __align__(16) unsigned char g_B2hi[40 * 528];
__device__ __align__(16) unsigned char g_B2lo[40 * 528];

// ---------------- helpers ----------------

__device__ __forceinline__ uint32_t smem_u32(const void* p) {
    uint32_t a;
    asm("{ .reg .u64 t; cvta.to.shared.u64 t, %1; cvt.u32.u64 %0, t; }"
        : "=r"(a) : "l"(p));
    return a;
}

__device__ __forceinline__ void split_bf16(float v, __nv_bfloat16& h,
                                           __nv_bfloat16& l) {
    h = __float2bfloat16(v);
    l = __float2bfloat16(v - __bfloat162float(h));
}
__device__ __forceinline__ uint32_t pack2(__nv_bfloat16 a, __nv_bfloat16 b) {
    return ((uint32_t)__bfloat16_as_ushort(b) << 16) |
           (uint32_t)__bfloat16_as_ushort(a);
}

#define LDSM4(r, addr)                                                         \
    asm volatile("ldmatrix.sync.aligned.m8n8.x4.shared.b16 {%0,%1,%2,%3},[%4];"\
                 : "=r"((r)[0]), "=r"((r)[1]), "=r"((r)[2]), "=r"((r)[3])      \
                 : "r"(addr))
#define LDSM2(r, addr)                                                         \
    asm volatile("ldmatrix.sync.aligned.m8n8.x2.shared.b16 {%0,%1},[%2];"      \
                 : "=r"((r)[0]), "=r"((r)[1]) : "r"(addr))
#define MMA16816(d, a, b)                                                      \
    asm volatile(                                                              \
        "mma.sync.aligned.m16n8k16.row.col.f32.bf16.bf16.f32 "                 \
        "{%0,%1,%2,%3},{%4,%5,%6,%7},{%8,%9},{%0,%1,%2,%3};"                   \
        : "+f"((d)[0]), "+f"((d)[1]), "+f"((d)[2]), "+f"((d)[3])               \
        : "r"((a)[0]), "r"((a)[1]), "r"((a)[2]), "r"((a)[3]),                  \
          "r"((b)[0]), "r"((b)[1]))

// ---------------- mapping pipeline (unchanged, verified) ----------------

__global__ void k_init_firstpos() {
    int i = blockIdx.x * blockDim.x + threadIdx.x;
    if (i < NN) g_first_pos[i] = NN;
}

__global__ void k_firstpos(const int* __restrict__ ei) {
    int i = blockIdx.x * blockDim.x + threadIdx.x;
    if (i < NN) atomicMin(&g_first_pos[ei[2 * i]], i);
}

__global__ __launch_bounds__(256) void k_scan1(const int* __restrict__ ei) {
    int t = threadIdx.x, b = blockIdx.x;
    int base = b * IPB + t * 8;
    int f[8]; int ls = 0;
#pragma unroll
    for (int j = 0; j < 8; j++) {
        int i = base + j;
        int v = 0;
        if (i < NN) { int s = ei[2 * i]; v = (g_first_pos[s] == i) ? 1 : 0; }
        f[j] = v; ls += v;
    }
    int lane = t & 31, wid = t >> 5;
    int incl = ls;
#pragma unroll
    for (int o = 1; o < 32; o <<= 1) {
        int n = __shfl_up_sync(0xffffffffu, incl, o);
        if (lane >= o) incl += n;
    }
    __shared__ int wtot[8], woff[8];
    if (lane == 31) wtot[wid] = incl;
    __syncthreads();
    if (t < 8) {
        int s = 0;
        for (int j = 0; j < t; j++) s += wtot[j];
        woff[t] = s;
    }
    __syncthreads();
    int run = woff[wid] + (incl - ls);
#pragma unroll
    for (int j = 0; j < 8; j++) {
        int i = base + j;
        if (i < NN) g_excl[i] = run;
        run += f[j];
    }
    if (t == 255) g_bsum[b] = run;
}

__global__ __launch_bounds__(256) void k_scan2() {
    int t = threadIdx.x;
    int v = (t < NBLK) ? g_bsum[t] : 0;
    int lane = t & 31, wid = t >> 5;
    int incl = v;
#pragma unroll
    for (int o = 1; o < 32; o <<= 1) {
        int n = __shfl_up_sync(0xffffffffu, incl, o);
        if (lane >= o) incl += n;
    }
    __shared__ int wtot[8], woff[8];
    if (lane == 31) wtot[wid] = incl;
    __syncthreads();
    if (t < 8) {
        int s = 0;
        for (int j = 0; j < t; j++) s += wtot[j];
        woff[t] = s;
    }
    __syncthreads();
    int excl = woff[wid] + incl - v;
    if (t < NBLK) g_bsumx[t] = excl;
    if (t == 255) g_U = excl + v;
}

__global__ void k_mapped(const int* __restrict__ ei) {
    int i = blockIdx.x * blockDim.x + threadIdx.x;
    if (i < NN) {
        int j  = ei[2 * i];
        int s2 = ei[2 * j];
        int p  = g_first_pos[s2];
        g_mapped[i] = g_excl[p] + g_bsumx[p / IPB];
    }
}

__global__ void k_zero_agg() {
    size_t total = (size_t)g_U * HH / 4;
    float4* p = (float4*)g_agg;
    float4 z = make_float4(0.f, 0.f, 0.f, 0.f);
    for (size_t i = blockIdx.x * (size_t)blockDim.x + threadIdx.x; i < total;
         i += (size_t)gridDim.x * blockDim.x)
        p[i] = z;
}

// ---------------- weight prep: transpose + bf16 split, padded pitch ----------------

__global__ void k_prep1(const float* __restrict__ W1) {
    int idx = blockIdx.x * blockDim.x + threadIdx.x;   // 256*128
    if (idx >= HH * FF) return;
    int n = idx >> 7, k = idx & 127;
    float v = W1[(size_t)k * HH + n];
    __nv_bfloat16 h, l; split_bf16(v, h, l);
    uint32_t off = (uint32_t)n * 272 + (uint32_t)k * 2;
    *(unsigned short*)(g_B1hi + off) = __bfloat16_as_ushort(h);
    *(unsigned short*)(g_B1lo + off) = __bfloat16_as_ushort(l);
}

__global__ void k_prep2(const float* __restrict__ W2) {
    int idx = blockIdx.x * blockDim.x + threadIdx.x;   // 40*256
    if (idx >= CC * HH) return;
    int n = idx >> 8, k = idx & 255;
    float v = W2[(size_t)k * CC + n];
    __nv_bfloat16 h, l; split_bf16(v, h, l);
    uint32_t off = (uint32_t)n * 528 + (uint32_t)k * 2;
    *(unsigned short*)(g_B2hi + off) = __bfloat16_as_ushort(h);
    *(unsigned short*)(g_B2lo + off) = __bfloat16_as_ushort(l);
}

// ---------------- GEMM1 (HMMA): relu(x@W1+b1) fused scatter ----------------
// CTA: M=128 rows, N=128 cols (grid.y=2 covers H=256), K=128.
// 3 chains (hh, hl, lh) x 8 k16 steps. Warp tile 32x64.
#define G1_SMEM 139264    // Ah(34816)+Al(34816)+Bh(34816)+Bl(34816)

__global__ __launch_bounds__(256, 1)
void k_g1(const float* __restrict__ x, const float* __restrict__ b1) {
    extern __shared__ __align__(16) char sm[];
    __shared__ float sb1[128];
    uint32_t sAh = smem_u32(sm);
    uint32_t sAl = sAh + 34816;
    uint32_t sBh = sAh + 69632;
    uint32_t sBl = sAh + 104448;

    int tid = threadIdx.x, lane = tid & 31, wid = tid >> 5;
    int rowBase = blockIdx.x * 128, colBase = blockIdx.y * 128;

    if (tid < 128) sb1[tid] = b1[colBase + tid];

    // copy pre-split B slice (rows colBase..colBase+127), pitch 272B
    {
        const uint4* srcH = (const uint4*)(g_B1hi + (size_t)colBase * 272);
        const uint4* srcL = (const uint4*)(g_B1lo + (size_t)colBase * 272);
        uint4* dH = (uint4*)(sm + 69632);
        uint4* dL = (uint4*)(sm + 104448);
#pragma unroll
        for (int i = tid; i < 2176; i += 256) { dH[i] = srcH[i]; dL[i] = srcL[i]; }
    }
    // stage A: split x rows into bf16 hi/lo, pitch 272B
#pragma unroll
    for (int q = tid; q < 2048; q += 256) {
        int m = q >> 4, g = q & 15;
        int row = rowBase + m;
        float a[8];
        if (row < NN) {
            float4 v0 = *(const float4*)&x[(size_t)row * FF + g * 8];
            float4 v1 = *(const float4*)&x[(size_t)row * FF + g * 8 + 4];
            a[0] = v0.x; a[1] = v0.y; a[2] = v0.z; a[3] = v0.w;
            a[4] = v1.x; a[5] = v1.y; a[6] = v1.z; a[7] = v1.w;
        } else {
#pragma unroll
            for (int j = 0; j < 8; j++) a[j] = 0.f;
        }
        __nv_bfloat16 h[8], l[8];
#pragma unroll
        for (int j = 0; j < 8; j++) split_bf16(a[j], h[j], l[j]);
        uint4 ph, pl;
        ph.x = pack2(h[0], h[1]); ph.y = pack2(h[2], h[3]);
        ph.z = pack2(h[4], h[5]); ph.w = pack2(h[6], h[7]);
        pl.x = pack2(l[0], l[1]); pl.y = pack2(l[2], l[3]);
        pl.z = pack2(l[4], l[5]); pl.w = pack2(l[6], l[7]);
        *(uint4*)(sm + m * 272 + g * 16)         = ph;
        *(uint4*)(sm + 34816 + m * 272 + g * 16) = pl;
    }
    __syncthreads();

    int mRow = (wid & 3) * 32, nCol = (wid >> 2) * 64;
    float acc[2][8][4];
#pragma unroll
    for (int i = 0; i < 2; i++)
#pragma unroll
        for (int j = 0; j < 8; j++)
#pragma unroll
            for (int e = 0; e < 4; e++) acc[i][j][e] = 0.f;

#pragma unroll
    for (int c = 0; c < 3; c++) {
        uint32_t Ab = (c == 2) ? sAl : sAh;
        uint32_t Bb = (c == 1) ? sBl : sBh;
#pragma unroll
        for (int ks = 0; ks < 8; ks++) {
            uint32_t af[2][4];
#pragma unroll
            for (int mt = 0; mt < 2; mt++) {
                uint32_t ad = Ab + (mRow + mt * 16 + (lane & 15)) * 272 +
                              (ks * 16 + (lane >> 4) * 8) * 2;
                LDSM4(af[mt], ad);
            }
            uint32_t bf[8][2];
#pragma unroll
            for (int p = 0; p < 4; p++) {
                uint32_t r4[4];
                uint32_t bd = Bb +
                    (nCol + p * 16 + ((lane >> 4) & 1) * 8 + (lane & 7)) * 272 +
                    (ks * 16 + ((lane >> 3) & 1) * 8) * 2;
                LDSM4(r4, bd);
                bf[2 * p][0] = r4[0]; bf[2 * p][1] = r4[1];
                bf[2 * p + 1][0] = r4[2]; bf[2 * p + 1][1] = r4[3];
            }
#pragma unroll
            for (int mt = 0; mt < 2; mt++)
#pragma unroll
                for (int nt = 0; nt < 8; nt++)
                    MMA16816(acc[mt][nt], af[mt], bf[nt]);
        }
    }
    __syncthreads();   // before overwriting A region with Cs

    // stage acc to smem (Cs: 128 rows x pitch 132 floats = 528B, fits in Ah+Al)
    float* Cs = (float*)sm;
#pragma unroll
    for (int mt = 0; mt < 2; mt++)
#pragma unroll
        for (int nt = 0; nt < 8; nt++) {
            int r = mRow + mt * 16 + (lane >> 2);
            int cc = nCol + nt * 8 + (lane & 3) * 2;
            *(float2*)&Cs[r * 132 + cc] =
                make_float2(acc[mt][nt][0], acc[mt][nt][1]);
            *(float2*)&Cs[(r + 8) * 132 + cc] =
                make_float2(acc[mt][nt][2], acc[mt][nt][3]);
        }
    __syncthreads();

    // scatter: bias + relu + red.global.add.v4 into agg[mapped[row]]
    int row = tid & 127, half = tid >> 7;
    int grow = rowBase + row;
    if (grow < NN) {
        int tgt = g_mapped[grow];
        float* dst = g_agg + (size_t)tgt * HH + colBase + half * 64;
        const float* csrc = Cs + row * 132 + half * 64;
#pragma unroll
        for (int q = 0; q < 16; q++) {
            float4 v = *(const float4*)&csrc[q * 4];
            int cb = half * 64 + q * 4;
            v.x = fmaxf(v.x + sb1[cb], 0.f);
            v.y = fmaxf(v.y + sb1[cb + 1], 0.f);
            v.z = fmaxf(v.z + sb1[cb + 2], 0.f);
            v.w = fmaxf(v.w + sb1[cb + 3], 0.f);
            asm volatile("red.global.add.v4.f32 [%0], {%1,%2,%3,%4};" ::
                         "l"(dst + q * 4), "f"(v.x), "f"(v.y), "f"(v.z),
                         "f"(v.w) : "memory");
        }
    }
}

// ---------------- GEMM2 (HMMA): out = relu(agg)@W2 + b2 ----------------
// CTA: M=128, N=40 (5 n8 tiles exactly), K=256. Warp tile 16x40.
#define G2_SMEM 177408    // Ah(67584)+Al(67584)+Bh(21120)+Bl(21120)

__global__ __launch_bounds__(256, 1)
void k_g2(const float* __restrict__ b2, float* __restrict__ out) {
    extern __shared__ __align__(16) char sm[];
    __shared__ float sb2[CC];
    uint32_t sAh = smem_u32(sm);
    uint32_t sAl = sAh + 67584;
    uint32_t sBh = sAh + 135168;
    uint32_t sBl = sAh + 156288;

    int tid = threadIdx.x, lane = tid & 31, wid = tid >> 5;
    int rowBase = blockIdx.x * 128;
    int U = g_U;

    if (tid < CC) sb2[tid] = b2[tid];

    {
        const uint4* srcH = (const uint4*)g_B2hi;
        const uint4* srcL = (const uint4*)g_B2lo;
        uint4* dH = (uint4*)(sm + 135168);
        uint4* dL = (uint4*)(sm + 156288);
#pragma unroll
        for (int i = tid; i < 1320; i += 256) { dH[i] = srcH[i]; dL[i] = srcL[i]; }
    }
    // stage A = relu(agg) split; rows >= U are zeros; pitch 528B
#pragma unroll
    for (int q = tid; q < 4096; q += 256) {
        int m = q >> 5, g = q & 31;
        int row = rowBase + m;
        float a[8];
        if (row < U) {
            float4 v0 = *(const float4*)&g_agg[(size_t)row * HH + g * 8];
            float4 v1 = *(const float4*)&g_agg[(size_t)row * HH + g * 8 + 4];
            a[0] = fmaxf(v0.x, 0.f); a[1] = fmaxf(v0.y, 0.f);
            a[2] = fmaxf(v0.z, 0.f); a[3] = fmaxf(v0.w, 0.f);
            a[4] = fmaxf(v1.x, 0.f); a[5] = fmaxf(v1.y, 0.f);
            a[6] = fmaxf(v1.z, 0.f); a[7] = fmaxf(v1.w, 0.f);
        } else {
#pragma unroll
            for (int j = 0; j < 8; j++) a[j] = 0.f;
        }
        __nv_bfloat16 h[8], l[8];
#pragma unroll
        for (int j = 0; j < 8; j++) split_bf16(a[j], h[j], l[j]);
        uint4 ph, pl;
        ph.x = pack2(h[0], h[1]); ph.y = pack2(h[2], h[3]);
        ph.z = pack2(h[4], h[5]); ph.w = pack2(h[6], h[7]);
        pl.x = pack2(l[0], l[1]); pl.y = pack2(l[2], l[3]);
        pl.z = pack2(l[4], l[5]); pl.w = pack2(l[6], l[7]);
        *(uint4*)(sm + m * 528 + g * 16)         = ph;
        *(uint4*)(sm + 67584 + m * 528 + g * 16) = pl;
    }
    __syncthreads();

    int m0 = wid * 16;
    float acc[5][4];
#pragma unroll
    for (int j = 0; j < 5; j++)
#pragma unroll
        for (int e = 0; e < 4; e++) acc[j][e] = 0.f;

#pragma unroll
    for (int c = 0; c < 3; c++) {
        uint32_t Ab = (c == 2) ? sAl : sAh;
        uint32_t Bb = (c == 1) ? sBl : sBh;
#pragma unroll
        for (int ks = 0; ks < 16; ks++) {
            uint32_t af[4];
            uint32_t ad = Ab + (m0 + (lane & 15)) * 528 +
                          (ks * 16 + (lane >> 4) * 8) * 2;
            LDSM4(af, ad);
            uint32_t bf[5][2];
#pragma unroll
            for (int p = 0; p < 2; p++) {
                uint32_t r4[4];
                uint32_t bd = Bb +
                    (p * 16 + ((lane >> 4) & 1) * 8 + (lane & 7)) * 528 +
                    (ks * 16 + ((lane >> 3) & 1) * 8) * 2;
                LDSM4(r4, bd);
                bf[2 * p][0] = r4[0]; bf[2 * p][1] = r4[1];
                bf[2 * p + 1][0] = r4[2]; bf[2 * p + 1][1] = r4[3];
            }
            {
                uint32_t bd2 = Bb + (32 + (lane & 7)) * 528 +
                               (ks * 16 + ((lane >> 3) & 1) * 8) * 2;
                LDSM2(bf[4], bd2);
            }
#pragma unroll
            for (int nt = 0; nt < 5; nt++) MMA16816(acc[nt], af, bf[nt]);
        }
    }

    // epilogue: direct stores with bias
    int r0 = m0 + (lane >> 2);
#pragma unroll
    for (int nt = 0; nt < 5; nt++) {
        int col = nt * 8 + (lane & 3) * 2;
        float bx = sb2[col], by = sb2[col + 1];
        int gA = rowBase + r0, gB = gA + 8;
        if (gA < NN)
            *(float2*)&out[(size_t)gA * CC + col] =
                make_float2(acc[nt][0] + bx, acc[nt][1] + by);
        if (gB < NN)
            *(float2*)&out[(size_t)gB * CC + col] =
                make_float2(acc[nt][2] + bx, acc[nt][3] + by);
    }
}

// ---------------- launch ----------------
extern "C" void kernel_launch(void* const* d_in, const int* in_sizes, int n_in,
                              void* d_out, int out_size) {
    const float* x  = (const float*)d_in[0];
    const int*   ei = (const int*)d_in[1];
    const float* W1 = (const float*)d_in[2];
    const float* b1 = (const float*)d_in[3];
    const float* W2 = (const float*)d_in[4];
    const float* b2 = (const float*)d_in[5];
    float* out = (float*)d_out;

    cudaFuncSetAttribute(k_g1, cudaFuncAttributeMaxDynamicSharedMemorySize,
                         G1_SMEM);
    cudaFuncSetAttribute(k_g2, cudaFuncAttributeMaxDynamicSharedMemorySize,
                         G2_SMEM);

    int nb = (NN + 255) / 256;
    k_init_firstpos<<<nb, 256>>>();
    k_firstpos<<<nb, 256>>>(ei);
    k_scan1<<<NBLK, 256>>>(ei);
    k_scan2<<<1, 256>>>();
    k_mapped<<<nb, 256>>>(ei);
    k_zero_agg<<<2048, 256>>>();
    k_prep1<<<(HH * FF + 255) / 256, 256>>>(W1);
    k_prep2<<<(CC * HH + 255) / 256, 256>>>(W2);

    int rowTiles = (NN + 127) / 128;   // 3907
    dim3 g1(rowTiles, 2);
    k_g1<<<g1, 256, G1_SMEM>>>(x, b1);
    k_g2<<<rowTiles, 256, G2_SMEM>>>(b2, out);
}

// round 7
// speedup vs baseline: 2.6179x; 1.5693x over previous
#include <cuda_runtime.h>
#include <cuda_fp16.h>
#include <cstdint>

#define NN 500000
#define FF 128
#define HH 256
#define CC 40
#define IPB 2048                       // items per scan block (256 thr x 8)
#define NBLK ((NN + IPB - 1) / IPB)    // 245

static_assert(NBLK <= 256, "scan2 single block");

// ---- scratch (device globals; no allocations allowed) ----
__device__ int g_first_pos[NN];
__device__ int g_excl[NN];
__device__ int g_bsum[NBLK];
__device__ int g_bsumx[NBLK];
__device__ int g_mapped[NN];
__device__ int g_U;
__device__ __align__(128) float g_agg[(size_t)NN * HH];   // 512 MB

// pre-converted fp16 W images, transposed to [n][k] with ldmatrix pitch
// pitch1 = 272 B (272 % 128 == 16 -> conflict-free ldmatrix)
// pitch2 = 528 B (528 % 128 == 16)
__device__ __align__(16) unsigned char g_B1h[256 * 272];
__device__ __align__(16) unsigned char g_B2h[40 * 528];

// ---------------- helpers ----------------

__device__ __forceinline__ uint32_t smem_u32(const void* p) {
    uint32_t a;
    asm("{ .reg .u64 t; cvta.to.shared.u64 t, %1; cvt.u32.u64 %0, t; }"
        : "=r"(a) : "l"(p));
    return a;
}

__device__ __forceinline__ uint32_t pack2h(__half a, __half b) {
    return ((uint32_t)__half_as_ushort(b) << 16) |
           (uint32_t)__half_as_ushort(a);
}

#define LDSM4(r, addr)                                                         \
    asm volatile("ldmatrix.sync.aligned.m8n8.x4.shared.b16 {%0,%1,%2,%3},[%4];"\
                 : "=r"((r)[0]), "=r"((r)[1]), "=r"((r)[2]), "=r"((r)[3])      \
                 : "r"(addr))
#define LDSM2(r, addr)                                                         \
    asm volatile("ldmatrix.sync.aligned.m8n8.x2.shared.b16 {%0,%1},[%2];"      \
                 : "=r"((r)[0]), "=r"((r)[1]) : "r"(addr))
#define MMA16816(d, a, b)                                                      \
    asm volatile(                                                              \
        "mma.sync.aligned.m16n8k16.row.col.f32.f16.f16.f32 "                   \
        "{%0,%1,%2,%3},{%4,%5,%6,%7},{%8,%9},{%0,%1,%2,%3};"                   \
        : "+f"((d)[0]), "+f"((d)[1]), "+f"((d)[2]), "+f"((d)[3])               \
        : "r"((a)[0]), "r"((a)[1]), "r"((a)[2]), "r"((a)[3]),                  \
          "r"((b)[0]), "r"((b)[1]))

// ---------------- mapping pipeline (unchanged, verified) ----------------

__global__ void k_init_firstpos() {
    int i = blockIdx.x * blockDim.x + threadIdx.x;
    if (i < NN) g_first_pos[i] = NN;
}

__global__ void k_firstpos(const int* __restrict__ ei) {
    int i = blockIdx.x * blockDim.x + threadIdx.x;
    if (i < NN) atomicMin(&g_first_pos[ei[2 * i]], i);
}

__global__ __launch_bounds__(256) void k_scan1(const int* __restrict__ ei) {
    int t = threadIdx.x, b = blockIdx.x;
    int base = b * IPB + t * 8;
    int f[8]; int ls = 0;
#pragma unroll
    for (int j = 0; j < 8; j++) {
        int i = base + j;
        int v = 0;
        if (i < NN) { int s = ei[2 * i]; v = (g_first_pos[s] == i) ? 1 : 0; }
        f[j] = v; ls += v;
    }
    int lane = t & 31, wid = t >> 5;
    int incl = ls;
#pragma unroll
    for (int o = 1; o < 32; o <<= 1) {
        int n = __shfl_up_sync(0xffffffffu, incl, o);
        if (lane >= o) incl += n;
    }
    __shared__ int wtot[8], woff[8];
    if (lane == 31) wtot[wid] = incl;
    __syncthreads();
    if (t < 8) {
        int s = 0;
        for (int j = 0; j < t; j++) s += wtot[j];
        woff[t] = s;
    }
    __syncthreads();
    int run = woff[wid] + (incl - ls);
#pragma unroll
    for (int j = 0; j < 8; j++) {
        int i = base + j;
        if (i < NN) g_excl[i] = run;
        run += f[j];
    }
    if (t == 255) g_bsum[b] = run;
}

__global__ __launch_bounds__(256) void k_scan2() {
    int t = threadIdx.x;
    int v = (t < NBLK) ? g_bsum[t] : 0;
    int lane = t & 31, wid = t >> 5;
    int incl = v;
#pragma unroll
    for (int o = 1; o < 32; o <<= 1) {
        int n = __shfl_up_sync(0xffffffffu, incl, o);
        if (lane >= o) incl += n;
    }
    __shared__ int wtot[8], woff[8];
    if (lane == 31) wtot[wid] = incl;
    __syncthreads();
    if (t < 8) {
        int s = 0;
        for (int j = 0; j < t; j++) s += wtot[j];
        woff[t] = s;
    }
    __syncthreads();
    int excl = woff[wid] + incl - v;
    if (t < NBLK) g_bsumx[t] = excl;
    if (t == 255) g_U = excl + v;
}

__global__ void k_mapped(const int* __restrict__ ei) {
    int i = blockIdx.x * blockDim.x + threadIdx.x;
    if (i < NN) {
        int j  = ei[2 * i];
        int s2 = ei[2 * j];
        int p  = g_first_pos[s2];
        g_mapped[i] = g_excl[p] + g_bsumx[p / IPB];
    }
}

__global__ void k_zero_agg() {
    size_t total = (size_t)g_U * HH / 4;
    float4* p = (float4*)g_agg;
    float4 z = make_float4(0.f, 0.f, 0.f, 0.f);
    for (size_t i = blockIdx.x * (size_t)blockDim.x + threadIdx.x; i < total;
         i += (size_t)gridDim.x * blockDim.x)
        p[i] = z;
}

// ---------------- weight prep: transpose + fp16, padded pitch ----------------

__global__ void k_prep1(const float* __restrict__ W1) {
    int idx = blockIdx.x * blockDim.x + threadIdx.x;   // 256*128
    if (idx >= HH * FF) return;
    int n = idx >> 7, k = idx & 127;
    float v = W1[(size_t)k * HH + n];
    uint32_t off = (uint32_t)n * 272 + (uint32_t)k * 2;
    *(unsigned short*)(g_B1h + off) = __half_as_ushort(__float2half_rn(v));
}

__global__ void k_prep2(const float* __restrict__ W2) {
    int idx = blockIdx.x * blockDim.x + threadIdx.x;   // 40*256
    if (idx >= CC * HH) return;
    int n = idx >> 8, k = idx & 255;
    float v = W2[(size_t)k * CC + n];
    uint32_t off = (uint32_t)n * 528 + (uint32_t)k * 2;
    *(unsigned short*)(g_B2h + off) = __half_as_ushort(__float2half_rn(v));
}

// ---------------- GEMM1 (HMMA fp16): relu(x@W1+b1) fused scatter ----------------
// CTA: M=128 rows, N=128 cols (grid.y=2 covers H=256), K=128. Warp tile 32x64.
#define G1_SMEM 69632    // A(34816)+B(34816); Cs(67584) reuses it

__global__ __launch_bounds__(256, 2)
void k_g1(const float* __restrict__ x, const float* __restrict__ b1) {
    extern __shared__ __align__(16) char sm[];
    __shared__ float sb1[128];
    uint32_t sA = smem_u32(sm);
    uint32_t sB = sA + 34816;

    int tid = threadIdx.x, lane = tid & 31, wid = tid >> 5;
    int rowBase = blockIdx.x * 128, colBase = blockIdx.y * 128;

    if (tid < 128) sb1[tid] = b1[colBase + tid];

    // copy pre-converted B slice (rows colBase..colBase+127), pitch 272B
    {
        const uint4* srcH = (const uint4*)(g_B1h + (size_t)colBase * 272);
        uint4* dH = (uint4*)(sm + 34816);
#pragma unroll
        for (int i = tid; i < 2176; i += 256) dH[i] = srcH[i];
    }
    // stage A: convert x rows to fp16, pitch 272B
#pragma unroll
    for (int q = tid; q < 2048; q += 256) {
        int m = q >> 4, g = q & 15;
        int row = rowBase + m;
        float a[8];
        if (row < NN) {
            float4 v0 = *(const float4*)&x[(size_t)row * FF + g * 8];
            float4 v1 = *(const float4*)&x[(size_t)row * FF + g * 8 + 4];
            a[0] = v0.x; a[1] = v0.y; a[2] = v0.z; a[3] = v0.w;
            a[4] = v1.x; a[5] = v1.y; a[6] = v1.z; a[7] = v1.w;
        } else {
#pragma unroll
            for (int j = 0; j < 8; j++) a[j] = 0.f;
        }
        uint4 ph;
        ph.x = pack2h(__float2half_rn(a[0]), __float2half_rn(a[1]));
        ph.y = pack2h(__float2half_rn(a[2]), __float2half_rn(a[3]));
        ph.z = pack2h(__float2half_rn(a[4]), __float2half_rn(a[5]));
        ph.w = pack2h(__float2half_rn(a[6]), __float2half_rn(a[7]));
        *(uint4*)(sm + m * 272 + g * 16) = ph;
    }
    __syncthreads();

    int mRow = (wid & 3) * 32, nCol = (wid >> 2) * 64;
    float acc[2][8][4];
#pragma unroll
    for (int i = 0; i < 2; i++)
#pragma unroll
        for (int j = 0; j < 8; j++)
#pragma unroll
            for (int e = 0; e < 4; e++) acc[i][j][e] = 0.f;

#pragma unroll
    for (int ks = 0; ks < 8; ks++) {
        uint32_t af[2][4];
#pragma unroll
        for (int mt = 0; mt < 2; mt++) {
            uint32_t ad = sA + (mRow + mt * 16 + (lane & 15)) * 272 +
                          (ks * 16 + (lane >> 4) * 8) * 2;
            LDSM4(af[mt], ad);
        }
        uint32_t bf[8][2];
#pragma unroll
        for (int p = 0; p < 4; p++) {
            uint32_t r4[4];
            uint32_t bd = sB +
                (nCol + p * 16 + ((lane >> 4) & 1) * 8 + (lane & 7)) * 272 +
                (ks * 16 + ((lane >> 3) & 1) * 8) * 2;
            LDSM4(r4, bd);
            bf[2 * p][0] = r4[0]; bf[2 * p][1] = r4[1];
            bf[2 * p + 1][0] = r4[2]; bf[2 * p + 1][1] = r4[3];
        }
#pragma unroll
        for (int mt = 0; mt < 2; mt++)
#pragma unroll
            for (int nt = 0; nt < 8; nt++)
                MMA16816(acc[mt][nt], af[mt], bf[nt]);
    }
    __syncthreads();   // before overwriting A/B region with Cs

    // stage acc to smem (Cs: 128 rows x pitch 132 floats, fits in A+B)
    float* Cs = (float*)sm;
#pragma unroll
    for (int mt = 0; mt < 2; mt++)
#pragma unroll
        for (int nt = 0; nt < 8; nt++) {
            int r = mRow + mt * 16 + (lane >> 2);
            int cc = nCol + nt * 8 + (lane & 3) * 2;
            *(float2*)&Cs[r * 132 + cc] =
                make_float2(acc[mt][nt][0], acc[mt][nt][1]);
            *(float2*)&Cs[(r + 8) * 132 + cc] =
                make_float2(acc[mt][nt][2], acc[mt][nt][3]);
        }
    __syncthreads();

    // scatter: bias + relu + red.global.add.v4 into agg[mapped[row]]
    int row = tid & 127, half = tid >> 7;
    int grow = rowBase + row;
    if (grow < NN) {
        int tgt = g_mapped[grow];
        float* dst = g_agg + (size_t)tgt * HH + colBase + half * 64;
        const float* csrc = Cs + row * 132 + half * 64;
#pragma unroll
        for (int q = 0; q < 16; q++) {
            float4 v = *(const float4*)&csrc[q * 4];
            int cb = half * 64 + q * 4;
            v.x = fmaxf(v.x + sb1[cb], 0.f);
            v.y = fmaxf(v.y + sb1[cb + 1], 0.f);
            v.z = fmaxf(v.z + sb1[cb + 2], 0.f);
            v.w = fmaxf(v.w + sb1[cb + 3], 0.f);
            asm volatile("red.global.add.v4.f32 [%0], {%1,%2,%3,%4};" ::
                         "l"(dst + q * 4), "f"(v.x), "f"(v.y), "f"(v.z),
                         "f"(v.w) : "memory");
        }
    }
}

// ---------------- GEMM2 (HMMA fp16): out = relu(agg)@W2 + b2 ----------------
// CTA: M=128, N=40 (5 n8 tiles exactly), K=256. Warp tile 16x40.
#define G2_SMEM 88704    // A(67584)+B(21120)

__global__ __launch_bounds__(256, 2)
void k_g2(const float* __restrict__ b2, float* __restrict__ out) {
    extern __shared__ __align__(16) char sm[];
    __shared__ float sb2[CC];
    uint32_t sA = smem_u32(sm);
    uint32_t sB = sA + 67584;

    int tid = threadIdx.x, lane = tid & 31, wid = tid >> 5;
    int rowBase = blockIdx.x * 128;
    int U = g_U;

    if (tid < CC) sb2[tid] = b2[tid];

    // early-out: entire tile beyond live segments -> out = b2
    if (rowBase >= U) {
        __syncthreads();
#pragma unroll
        for (int q = tid; q < 128 * CC; q += 256) {
            int r = q / CC, c = q - r * CC;
            int grow = rowBase + r;
            if (grow < NN) out[(size_t)grow * CC + c] = sb2[c];
        }
        return;
    }

    {
        const uint4* srcH = (const uint4*)g_B2h;
        uint4* dH = (uint4*)(sm + 67584);
#pragma unroll
        for (int i = tid; i < 1320; i += 256) dH[i] = srcH[i];
    }
    // stage A = relu(agg) fp16; rows >= U are zeros; pitch 528B
#pragma unroll
    for (int q = tid; q < 4096; q += 256) {
        int m = q >> 5, g = q & 31;
        int row = rowBase + m;
        float a[8];
        if (row < U) {
            float4 v0 = *(const float4*)&g_agg[(size_t)row * HH + g * 8];
            float4 v1 = *(const float4*)&g_agg[(size_t)row * HH + g * 8 + 4];
            a[0] = fmaxf(v0.x, 0.f); a[1] = fmaxf(v0.y, 0.f);
            a[2] = fmaxf(v0.z, 0.f); a[3] = fmaxf(v0.w, 0.f);
            a[4] = fmaxf(v1.x, 0.f); a[5] = fmaxf(v1.y, 0.f);
            a[6] = fmaxf(v1.z, 0.f); a[7] = fmaxf(v1.w, 0.f);
        } else {
#pragma unroll
            for (int j = 0; j < 8; j++) a[j] = 0.f;
        }
        uint4 ph;
        ph.x = pack2h(__float2half_rn(a[0]), __float2half_rn(a[1]));
        ph.y = pack2h(__float2half_rn(a[2]), __float2half_rn(a[3]));
        ph.z = pack2h(__float2half_rn(a[4]), __float2half_rn(a[5]));
        ph.w = pack2h(__float2half_rn(a[6]), __float2half_rn(a[7]));
        *(uint4*)(sm + m * 528 + g * 16) = ph;
    }
    __syncthreads();

    int m0 = wid * 16;
    float acc[5][4];
#pragma unroll
    for (int j = 0; j < 5; j++)
#pragma unroll
        for (int e = 0; e < 4; e++) acc[j][e] = 0.f;

#pragma unroll
    for (int ks = 0; ks < 16; ks++) {
        uint32_t af[4];
        uint32_t ad = sA + (m0 + (lane & 15)) * 528 +
                      (ks * 16 + (lane >> 4) * 8) * 2;
        LDSM4(af, ad);
        uint32_t bf[5][2];
#pragma unroll
        for (int p = 0; p < 2; p++) {
            uint32_t r4[4];
            uint32_t bd = sB +
                (p * 16 + ((lane >> 4) & 1) * 8 + (lane & 7)) * 528 +
                (ks * 16 + ((lane >> 3) & 1) * 8) * 2;
            LDSM4(r4, bd);
            bf[2 * p][0] = r4[0]; bf[2 * p][1] = r4[1];
            bf[2 * p + 1][0] = r4[2]; bf[2 * p + 1][1] = r4[3];
        }
        {
            uint32_t bd2 = sB + (32 + (lane & 7)) * 528 +
                           (ks * 16 + ((lane >> 3) & 1) * 8) * 2;
            LDSM2(bf[4], bd2);
        }
#pragma unroll
        for (int nt = 0; nt < 5; nt++) MMA16816(acc[nt], af, bf[nt]);
    }

    // epilogue: direct stores with bias
    int r0 = m0 + (lane >> 2);
#pragma unroll
    for (int nt = 0; nt < 5; nt++) {
        int col = nt * 8 + (lane & 3) * 2;
        float bx = sb2[col], by = sb2[col + 1];
        int gA = rowBase + r0, gB = gA + 8;
        if (gA < NN)
            *(float2*)&out[(size_t)gA * CC + col] =
                make_float2(acc[nt][0] + bx, acc[nt][1] + by);
        if (gB < NN)
            *(float2*)&out[(size_t)gB * CC + col] =
                make_float2(acc[nt][2] + bx, acc[nt][3] + by);
    }
}

// ---------------- launch ----------------
extern "C" void kernel_launch(void* const* d_in, const int* in_sizes, int n_in,
                              void* d_out, int out_size) {
    const float* x  = (const float*)d_in[0];
    const int*   ei = (const int*)d_in[1];
    const float* W1 = (const float*)d_in[2];
    const float* b1 = (const float*)d_in[3];
    const float* W2 = (const float*)d_in[4];
    const float* b2 = (const float*)d_in[5];
    float* out = (float*)d_out;

    cudaFuncSetAttribute(k_g1, cudaFuncAttributeMaxDynamicSharedMemorySize,
                         G1_SMEM);
    cudaFuncSetAttribute(k_g2, cudaFuncAttributeMaxDynamicSharedMemorySize,
                         G2_SMEM);

    int nb = (NN + 255) / 256;
    k_init_firstpos<<<nb, 256>>>();
    k_firstpos<<<nb, 256>>>(ei);
    k_scan1<<<NBLK, 256>>>(ei);
    k_scan2<<<1, 256>>>();
    k_mapped<<<nb, 256>>>(ei);
    k_zero_agg<<<2048, 256>>>();
    k_prep1<<<(HH * FF + 255) / 256, 256>>>(W1);
    k_prep2<<<(CC * HH + 255) / 256, 256>>>(W2);

    int rowTiles = (NN + 127) / 128;   // 3907
    dim3 g1(rowTiles, 2);
    k_g1<<<g1, 256, G1_SMEM>>>(x, b1);
    k_g2<<<rowTiles, 256, G2_SMEM>>>(b2, out);
}

// round 10
// speedup vs baseline: 3.9575x; 1.5117x over previous
#include <cuda_runtime.h>
#include <cuda_fp16.h>
#include <cstdint>

#define NN 500000
#define FF 128
#define HH 256
#define CC 40
#define IPB 2048                       // items per scan block (256 thr x 8)
#define NBLK ((NN + IPB - 1) / IPB)    // 245

static_assert(NBLK <= 256, "scan2 single block");

// ---- scratch (device globals; no allocations allowed) ----
__device__ int g_first_pos[NN];
__device__ int g_excl[NN];
__device__ int g_bsum[NBLK];
__device__ int g_bsumx[NBLK];
__device__ int g_mapped[NN];
__device__ int g_U;
__device__ __align__(128) __half g_aggh[(size_t)NN * HH];   // 256 MB fp16

// pre-converted fp16 W images, transposed to [n][k] with ldmatrix pitch
// pitch1 = 272 B (272 % 128 == 16 -> conflict-free ldmatrix)
// pitch2 = 528 B (528 % 128 == 16)
__device__ __align__(16) unsigned char g_B1h[256 * 272];
__device__ __align__(16) unsigned char g_B2h[40 * 528];

// ---------------- helpers ----------------

__device__ __forceinline__ uint32_t smem_u32(const void* p) {
    uint32_t a;
    asm("{ .reg .u64 t; cvta.to.shared.u64 t, %1; cvt.u32.u64 %0, t; }"
        : "=r"(a) : "l"(p));
    return a;
}

__device__ __forceinline__ uint32_t f2h2u(float a, float b) {
    __half2 h = __floats2half2_rn(a, b);
    return *reinterpret_cast<uint32_t*>(&h);
}

#define LDSM4(r, addr)                                                         \
    asm volatile("ldmatrix.sync.aligned.m8n8.x4.shared.b16 {%0,%1,%2,%3},[%4];"\
                 : "=r"((r)[0]), "=r"((r)[1]), "=r"((r)[2]), "=r"((r)[3])      \
                 : "r"(addr))
#define LDSM2(r, addr)                                                         \
    asm volatile("ldmatrix.sync.aligned.m8n8.x2.shared.b16 {%0,%1},[%2];"      \
                 : "=r"((r)[0]), "=r"((r)[1]) : "r"(addr))
#define MMA16816(d, a, b)                                                      \
    asm volatile(                                                              \
        "mma.sync.aligned.m16n8k16.row.col.f32.f16.f16.f32 "                   \
        "{%0,%1,%2,%3},{%4,%5,%6,%7},{%8,%9},{%0,%1,%2,%3};"                   \
        : "+f"((d)[0]), "+f"((d)[1]), "+f"((d)[2]), "+f"((d)[3])               \
        : "r"((a)[0]), "r"((a)[1]), "r"((a)[2]), "r"((a)[3]),                  \
          "r"((b)[0]), "r"((b)[1]))

// ---------------- mapping pipeline (unchanged, verified) ----------------

__global__ void k_init_firstpos() {
    int i = blockIdx.x * blockDim.x + threadIdx.x;
    if (i < NN) g_first_pos[i] = NN;
}

__global__ void k_firstpos(const int* __restrict__ ei) {
    int i = blockIdx.x * blockDim.x + threadIdx.x;
    if (i < NN) atomicMin(&g_first_pos[ei[2 * i]], i);
}

__global__ __launch_bounds__(256) void k_scan1(const int* __restrict__ ei) {
    int t = threadIdx.x, b = blockIdx.x;
    int base = b * IPB + t * 8;
    int f[8]; int ls = 0;
#pragma unroll
    for (int j = 0; j < 8; j++) {
        int i = base + j;
        int v = 0;
        if (i < NN) { int s = ei[2 * i]; v = (g_first_pos[s] == i) ? 1 : 0; }
        f[j] = v; ls += v;
    }
    int lane = t & 31, wid = t >> 5;
    int incl = ls;
#pragma unroll
    for (int o = 1; o < 32; o <<= 1) {
        int n = __shfl_up_sync(0xffffffffu, incl, o);
        if (lane >= o) incl += n;
    }
    __shared__ int wtot[8], woff[8];
    if (lane == 31) wtot[wid] = incl;
    __syncthreads();
    if (t < 8) {
        int s = 0;
        for (int j = 0; j < t; j++) s += wtot[j];
        woff[t] = s;
    }
    __syncthreads();
    int run = woff[wid] + (incl - ls);
#pragma unroll
    for (int j = 0; j < 8; j++) {
        int i = base + j;
        if (i < NN) g_excl[i] = run;
        run += f[j];
    }
    if (t == 255) g_bsum[b] = run;
}

__global__ __launch_bounds__(256) void k_scan2() {
    int t = threadIdx.x;
    int v = (t < NBLK) ? g_bsum[t] : 0;
    int lane = t & 31, wid = t >> 5;
    int incl = v;
#pragma unroll
    for (int o = 1; o < 32; o <<= 1) {
        int n = __shfl_up_sync(0xffffffffu, incl, o);
        if (lane >= o) incl += n;
    }
    __shared__ int wtot[8], woff[8];
    if (lane == 31) wtot[wid] = incl;
    __syncthreads();
    if (t < 8) {
        int s = 0;
        for (int j = 0; j < t; j++) s += wtot[j];
        woff[t] = s;
    }
    __syncthreads();
    int excl = woff[wid] + incl - v;
    if (t < NBLK) g_bsumx[t] = excl;
    if (t == 255) g_U = excl + v;
}

__global__ void k_mapped(const int* __restrict__ ei) {
    int i = blockIdx.x * blockDim.x + threadIdx.x;
    if (i < NN) {
        int j  = ei[2 * i];
        int s2 = ei[2 * j];
        int p  = g_first_pos[s2];
        g_mapped[i] = g_excl[p] + g_bsumx[p / IPB];
    }
}

// zero one 128-col half of agg for live rows [0, U)
__global__ void k_zero_half(int q) {
    int U = g_U;
    size_t total = (size_t)U * 16;         // 16 uint4 per row-half
    uint4* p = (uint4*)g_aggh;
    uint4 z = make_uint4(0, 0, 0, 0);
    for (size_t i = blockIdx.x * (size_t)blockDim.x + threadIdx.x; i < total;
         i += (size_t)gridDim.x * blockDim.x) {
        size_t row = i >> 4;
        int c = (int)(i & 15);
        p[row * 32 + q * 16 + c] = z;
    }
}

// ---------------- weight prep: transpose + fp16, padded pitch ----------------

__global__ void k_prep1(const float* __restrict__ W1) {
    int idx = blockIdx.x * blockDim.x + threadIdx.x;   // 256*128
    if (idx >= HH * FF) return;
    int n = idx >> 7, k = idx & 127;
    float v = W1[(size_t)k * HH + n];
    uint32_t off = (uint32_t)n * 272 + (uint32_t)k * 2;
    *(unsigned short*)(g_B1h + off) = __half_as_ushort(__float2half_rn(v));
}

__global__ void k_prep2(const float* __restrict__ W2) {
    int idx = blockIdx.x * blockDim.x + threadIdx.x;   // 40*256
    if (idx >= CC * HH) return;
    int n = idx >> 8, k = idx & 255;
    float v = W2[(size_t)k * CC + n];
    uint32_t off = (uint32_t)n * 528 + (uint32_t)k * 2;
    *(unsigned short*)(g_B2h + off) = __half_as_ushort(__float2half_rn(v));
}

// ---------------- GEMM1 (HMMA fp16): relu(x@W1+b1) fused scatter ----------------
// CTA: M=128 rows, N=128 cols, K=128. colTile passed as arg. Warp tile 32x64.
#define G1_SMEM 69632    // A(34816)+B(34816); Cs(67584) reuses it

__global__ __launch_bounds__(256, 2)
void k_g1(const float* __restrict__ x, const float* __restrict__ b1,
          int colTile) {
    extern __shared__ __align__(16) char sm[];
    __shared__ float sb1[128];
    uint32_t sA = smem_u32(sm);
    uint32_t sB = sA + 34816;

    int tid = threadIdx.x, lane = tid & 31, wid = tid >> 5;
    int rowBase = blockIdx.x * 128, colBase = colTile * 128;

    if (tid < 128) sb1[tid] = b1[colBase + tid];

    // copy pre-converted B slice (rows colBase..colBase+127), pitch 272B
    {
        const uint4* srcH = (const uint4*)(g_B1h + (size_t)colBase * 272);
        uint4* dH = (uint4*)(sm + 34816);
#pragma unroll
        for (int i = tid; i < 2176; i += 256) dH[i] = srcH[i];
    }
    // stage A: convert x rows to fp16, pitch 272B (streaming x loads)
#pragma unroll
    for (int q = tid; q < 2048; q += 256) {
        int m = q >> 4, g = q & 15;
        int row = rowBase + m;
        float a[8];
        if (row < NN) {
            float4 v0 = __ldcs((const float4*)&x[(size_t)row * FF + g * 8]);
            float4 v1 = __ldcs((const float4*)&x[(size_t)row * FF + g * 8 + 4]);
            a[0] = v0.x; a[1] = v0.y; a[2] = v0.z; a[3] = v0.w;
            a[4] = v1.x; a[5] = v1.y; a[6] = v1.z; a[7] = v1.w;
        } else {
#pragma unroll
            for (int j = 0; j < 8; j++) a[j] = 0.f;
        }
        uint4 ph;
        ph.x = f2h2u(a[0], a[1]);
        ph.y = f2h2u(a[2], a[3]);
        ph.z = f2h2u(a[4], a[5]);
        ph.w = f2h2u(a[6], a[7]);
        *(uint4*)(sm + m * 272 + g * 16) = ph;
    }
    __syncthreads();

    int mRow = (wid & 3) * 32, nCol = (wid >> 2) * 64;
    float acc[2][8][4];
#pragma unroll
    for (int i = 0; i < 2; i++)
#pragma unroll
        for (int j = 0; j < 8; j++)
#pragma unroll
            for (int e = 0; e < 4; e++) acc[i][j][e] = 0.f;

#pragma unroll
    for (int ks = 0; ks < 8; ks++) {
        uint32_t af[2][4];
#pragma unroll
        for (int mt = 0; mt < 2; mt++) {
            uint32_t ad = sA + (mRow + mt * 16 + (lane & 15)) * 272 +
                          (ks * 16 + (lane >> 4) * 8) * 2;
            LDSM4(af[mt], ad);
        }
        uint32_t bf[8][2];
#pragma unroll
        for (int p = 0; p < 4; p++) {
            uint32_t r4[4];
            uint32_t bd = sB +
                (nCol + p * 16 + ((lane >> 4) & 1) * 8 + (lane & 7)) * 272 +
                (ks * 16 + ((lane >> 3) & 1) * 8) * 2;
            LDSM4(r4, bd);
            bf[2 * p][0] = r4[0]; bf[2 * p][1] = r4[1];
            bf[2 * p + 1][0] = r4[2]; bf[2 * p + 1][1] = r4[3];
        }
#pragma unroll
        for (int mt = 0; mt < 2; mt++)
#pragma unroll
            for (int nt = 0; nt < 8; nt++)
                MMA16816(acc[mt][nt], af[mt], bf[nt]);
    }
    __syncthreads();   // before overwriting A/B region with Cs

    // stage acc to smem (Cs: 128 rows x pitch 132 floats, fits in A+B)
    float* Cs = (float*)sm;
#pragma unroll
    for (int mt = 0; mt < 2; mt++)
#pragma unroll
        for (int nt = 0; nt < 8; nt++) {
            int r = mRow + mt * 16 + (lane >> 2);
            int cc = nCol + nt * 8 + (lane & 3) * 2;
            *(float2*)&Cs[r * 132 + cc] =
                make_float2(acc[mt][nt][0], acc[mt][nt][1]);
            *(float2*)&Cs[(r + 8) * 132 + cc] =
                make_float2(acc[mt][nt][2], acc[mt][nt][3]);
        }
    __syncthreads();

    // scatter: bias + relu + red.global.add.v4.f16x2 into aggh[mapped[row]]
    int row = tid & 127, half = tid >> 7;
    int grow = rowBase + row;
    if (grow < NN) {
        int tgt = g_mapped[grow];
        __half* dst = g_aggh + (size_t)tgt * HH + colBase + half * 64;
        const float* csrc = Cs + row * 132 + half * 64;
#pragma unroll
        for (int q = 0; q < 8; q++) {
            float4 va = *(const float4*)&csrc[q * 8];
            float4 vb = *(const float4*)&csrc[q * 8 + 4];
            int cb = half * 64 + q * 8;
            uint32_t p0 = f2h2u(fmaxf(va.x + sb1[cb], 0.f),
                                fmaxf(va.y + sb1[cb + 1], 0.f));
            uint32_t p1 = f2h2u(fmaxf(va.z + sb1[cb + 2], 0.f),
                                fmaxf(va.w + sb1[cb + 3], 0.f));
            uint32_t p2 = f2h2u(fmaxf(vb.x + sb1[cb + 4], 0.f),
                                fmaxf(vb.y + sb1[cb + 5], 0.f));
            uint32_t p3 = f2h2u(fmaxf(vb.z + sb1[cb + 6], 0.f),
                                fmaxf(vb.w + sb1[cb + 7], 0.f));
            asm volatile(
                "red.global.add.noftz.v4.f16x2 [%0], {%1,%2,%3,%4};" ::
                "l"(dst + q * 8), "r"(p0), "r"(p1), "r"(p2), "r"(p3)
                : "memory");
        }
    }
}

// ---------------- GEMM2 (HMMA fp16): out = relu(aggh)@W2 + b2 ----------------
// CTA: M=128, N=40 (5 n8 tiles exactly), K=256. Warp tile 16x40.
#define G2_SMEM 88704    // A(67584)+B(21120)

__global__ __launch_bounds__(256, 2)
void k_g2(const float* __restrict__ b2, float* __restrict__ out) {
    extern __shared__ __align__(16) char sm[];
    __shared__ float sb2[CC];
    uint32_t sA = smem_u32(sm);
    uint32_t sB = sA + 67584;

    int tid = threadIdx.x, lane = tid & 31, wid = tid >> 5;
    int rowBase = blockIdx.x * 128;
    int U = g_U;

    if (tid < CC) sb2[tid] = b2[tid];

    // early-out: entire tile beyond live segments -> out = b2
    if (rowBase >= U) {
        __syncthreads();
#pragma unroll
        for (int q = tid; q < 128 * CC; q += 256) {
            int r = q / CC, c = q - r * CC;
            int grow = rowBase + r;
            if (grow < NN) out[(size_t)grow * CC + c] = sb2[c];
        }
        return;
    }

    {
        const uint4* srcH = (const uint4*)g_B2h;
        uint4* dH = (uint4*)(sm + 67584);
#pragma unroll
        for (int i = tid; i < 1320; i += 256) dH[i] = srcH[i];
    }
    // stage A = relu(aggh) directly in fp16; rows >= U are zeros; pitch 528B
    // each (m, g) handles one uint4 = 8 halves; 32 groups cover 256 halves/row
    {
        const __half2 z2 = __float2half2_rn(0.f);
#pragma unroll
        for (int q = tid; q < 4096; q += 256) {
            int m = q >> 5, g = q & 31;      // 8 halves per step
            int row = rowBase + m;
            uint4 v = make_uint4(0, 0, 0, 0);
            if (row < U) {
                v = *(const uint4*)&g_aggh[(size_t)row * HH + g * 8];
                __half2* h = (__half2*)&v;
#pragma unroll
                for (int e = 0; e < 4; e++) h[e] = __hmax2(h[e], z2);
            }
            *(uint4*)(sm + m * 528 + g * 16) = v;
        }
    }
    __syncthreads();

    int m0 = wid * 16;
    float acc[5][4];
#pragma unroll
    for (int j = 0; j < 5; j++)
#pragma unroll
        for (int e = 0; e < 4; e++) acc[j][e] = 0.f;

#pragma unroll
    for (int ks = 0; ks < 16; ks++) {
        uint32_t af[4];
        uint32_t ad = sA + (m0 + (lane & 15)) * 528 +
                      (ks * 16 + (lane >> 4) * 8) * 2;
        LDSM4(af, ad);
        uint32_t bf[5][2];
#pragma unroll
        for (int p = 0; p < 2; p++) {
            uint32_t r4[4];
            uint32_t bd = sB +
                (p * 16 + ((lane >> 4) & 1) * 8 + (lane & 7)) * 528 +
                (ks * 16 + ((lane >> 3) & 1) * 8) * 2;
            LDSM4(r4, bd);
            bf[2 * p][0] = r4[0]; bf[2 * p][1] = r4[1];
            bf[2 * p + 1][0] = r4[2]; bf[2 * p + 1][1] = r4[3];
        }
        {
            uint32_t bd2 = sB + (32 + (lane & 7)) * 528 +
                           (ks * 16 + ((lane >> 3) & 1) * 8) * 2;
            LDSM2(bf[4], bd2);
        }
#pragma unroll
        for (int nt = 0; nt < 5; nt++) MMA16816(acc[nt], af, bf[nt]);
    }

    // epilogue: direct stores with bias
    int r0 = m0 + (lane >> 2);
#pragma unroll
    for (int nt = 0; nt < 5; nt++) {
        int col = nt * 8 + (lane & 3) * 2;
        float bx = sb2[col], by = sb2[col + 1];
        int gA = rowBase + r0, gB = gA + 8;
        if (gA < NN)
            *(float2*)&out[(size_t)gA * CC + col] =
                make_float2(acc[nt][0] + bx, acc[nt][1] + by);
        if (gB < NN)
            *(float2*)&out[(size_t)gB * CC + col] =
                make_float2(acc[nt][2] + bx, acc[nt][3] + by);
    }
}

// ---------------- launch ----------------
extern "C" void kernel_launch(void* const* d_in, const int* in_sizes, int n_in,
                              void* d_out, int out_size) {
    const float* x  = (const float*)d_in[0];
    const int*   ei = (const int*)d_in[1];
    const float* W1 = (const float*)d_in[2];
    const float* b1 = (const float*)d_in[3];
    const float* W2 = (const float*)d_in[4];
    const float* b2 = (const float*)d_in[5];
    float* out = (float*)d_out;

    cudaFuncSetAttribute(k_g1, cudaFuncAttributeMaxDynamicSharedMemorySize,
                         G1_SMEM);
    cudaFuncSetAttribute(k_g2, cudaFuncAttributeMaxDynamicSharedMemorySize,
                         G2_SMEM);

    int nb = (NN + 255) / 256;
    k_init_firstpos<<<nb, 256>>>();
    k_firstpos<<<nb, 256>>>(ei);
    k_scan1<<<NBLK, 256>>>(ei);
    k_scan2<<<1, 256>>>();
    k_mapped<<<nb, 256>>>(ei);
    k_prep1<<<(HH * FF + 255) / 256, 256>>>(W1);
    k_prep2<<<(CC * HH + 255) / 256, 256>>>(W2);

    int rowTiles = (NN + 127) / 128;   // 3907
    // interleave: zero a column half right before the colTile that fills it,
    // so the atomics RMW against L2-resident zeroed lines (81 MB < L2).
    k_zero_half<<<2048, 256>>>(0);
    k_g1<<<rowTiles, 256, G1_SMEM>>>(x, b1, 0);
    k_zero_half<<<2048, 256>>>(1);
    k_g1<<<rowTiles, 256, G1_SMEM>>>(x, b1, 1);

    k_g2<<<rowTiles, 256, G2_SMEM>>>(b2, out);
}